// round 7
// baseline (speedup 1.0000x reference)
#include <cuda_runtime.h>

#define HD 64
#define NG 16
#define TILE 32
#define ETILE 64
#define APAD 34
#define SST 68
#define LN_EPS 1e-3f
#define NMAX 100000
#define EMAX 1600000
#define EDGE_GRID 592
#define CHUNK 512

typedef unsigned long long u64;
typedef unsigned int uint;

// persistent scratch (device globals; allocation is forbidden)
__device__ float g_h[NMAX * HD];
__device__ float g_P[NMAX * HD];
__device__ float g_pool[NMAX * HD];
__device__ float g_ctx[NG * HD];
__device__ int g_deg[NMAX];
__device__ int g_pos[NMAX];
__device__ int g_sortpos[EMAX];   // e -> sorted slot
__device__ int g_stgt[EMAX];      // sorted slot -> target node
__device__ float g_msg[(size_t)EMAX * HD];  // messages in sorted order

// ---------------- helpers ----------------
__device__ __forceinline__ u64 dup2(float x) {
    u64 r; unsigned xi = __float_as_uint(x);
    asm("mov.b64 %0, {%1, %1};" : "=l"(r) : "r"(xi));
    return r;
}
__device__ __forceinline__ float2 unpack2(u64 v) {
    unsigned lo, hi;
    asm("mov.b64 {%0, %1}, %2;" : "=r"(lo), "=r"(hi) : "l"(v));
    return make_float2(__uint_as_float(lo), __uint_as_float(hi));
}
__device__ __forceinline__ void ffma2(u64& d, u64 a, u64 b) {
    asm("fma.rn.f32x2 %0, %1, %2, %0;" : "+l"(d) : "l"(a), "l"(b));
}
__device__ __forceinline__ uint to_tf32(float f) {
    uint r; asm("cvt.rna.tf32.f32 %0, %1;" : "=r"(r) : "f"(f));
    return r;
}
__device__ __forceinline__ void mma_tf32(float c[4], uint a0, uint a1, uint a2, uint a3,
                                         uint b0, uint b1) {
    asm("mma.sync.aligned.m16n8k8.row.col.f32.tf32.tf32.f32 "
        "{%0,%1,%2,%3}, {%4,%5,%6,%7}, {%8,%9}, {%0,%1,%2,%3};"
        : "+f"(c[0]), "+f"(c[1]), "+f"(c[2]), "+f"(c[3])
        : "r"(a0), "r"(a1), "r"(a2), "r"(a3), "r"(b0), "r"(b1));
}
__device__ __forceinline__ void cpa16(uint dst, const void* src) {
    asm volatile("cp.async.ca.shared.global [%0], [%1], 16;" :: "r"(dst), "l"(src));
}
#define CP_COMMIT() asm volatile("cp.async.commit_group;" ::: "memory")

// ---------------- fp32 SIMT GEMM pieces (node-side kernels) ----------------
__device__ __forceinline__ void stage_w(const float* __restrict__ W, float* sW) {
    int t = threadIdx.x;
    float4* d4 = (float4*)sW;
    const float4* s4 = (const float4*)W;
#pragma unroll
    for (int i = 0; i < 8; i++) d4[t + i * 128] = s4[t + i * 128];
}
__device__ __forceinline__ void stage_xT(const float* __restrict__ X, float* sA, int valid) {
    int t = threadIdx.x;
#pragma unroll
    for (int i = 0; i < 4; i++) {
        int flat = 4 * t + 512 * i;
        int r = flat >> 6, k = flat & 63;
        float4 v = make_float4(0.f, 0.f, 0.f, 0.f);
        if (r < valid) v = *(const float4*)(X + flat);
        sA[(k + 0) * APAD + r] = v.x;
        sA[(k + 1) * APAD + r] = v.y;
        sA[(k + 2) * APAD + r] = v.z;
        sA[(k + 3) * APAD + r] = v.w;
    }
}
__device__ __forceinline__ void gemm_tile(const float* sA, const float* sW,
                                          int e0, int f0, u64 acc[2][4]) {
    const float* pA = sA + e0;
    const float* pW = sW + f0;
#pragma unroll 8
    for (int k = 0; k < 64; k++) {
        u64 a01 = *(const u64*)(pA);
        u64 a23 = *(const u64*)(pA + 2);
        float4 w = *(const float4*)(pW);
        u64 w0 = dup2(w.x), w1 = dup2(w.y), w2 = dup2(w.z), w3 = dup2(w.w);
        ffma2(acc[0][0], a01, w0); ffma2(acc[1][0], a23, w0);
        ffma2(acc[0][1], a01, w1); ffma2(acc[1][1], a23, w1);
        ffma2(acc[0][2], a01, w2); ffma2(acc[1][2], a23, w2);
        ffma2(acc[0][3], a01, w3); ffma2(acc[1][3], a23, w3);
        pA += APAD; pW += 64;
    }
}
__device__ __forceinline__ void acc_to_rows(u64 acc[2][4], float v[4][4]) {
#pragma unroll
    for (int p = 0; p < 2; p++)
#pragma unroll
        for (int j = 0; j < 4; j++) {
            float2 u = unpack2(acc[p][j]);
            v[2 * p][j] = u.x;
            v[2 * p + 1][j] = u.y;
        }
}

// ---------------- sort-by-target (slim: sortpos + sorted tgt only) ----------------
__global__ void k_zero_deg(int N) {
    int i = blockIdx.x * blockDim.x + threadIdx.x;
    if (i < N) g_deg[i] = 0;
}
__global__ void k_hist(const int* __restrict__ etgt, int E) {
    for (int e = blockIdx.x * blockDim.x + threadIdx.x; e < E;
         e += gridDim.x * blockDim.x)
        atomicAdd(&g_deg[etgt[e]], 1);
}
__global__ void k_scan(int N) {
    __shared__ int s[1024];
    int t = threadIdx.x;
    int carry = 0;
    int nch = (N + 1023) >> 10;
    for (int ch = 0; ch < nch; ch++) {
        int i = (ch << 10) + t;
        int v = (i < N) ? g_deg[i] : 0;
        s[t] = v; __syncthreads();
#pragma unroll
        for (int off = 1; off < 1024; off <<= 1) {
            int x = (t >= off) ? s[t - off] : 0;
            __syncthreads();
            s[t] += x; __syncthreads();
        }
        if (i < N) g_pos[i] = s[t] - v + carry;
        int tot = s[1023];
        __syncthreads();
        carry += tot;
    }
}
__global__ void k_scatter(const int* __restrict__ etgt, int E) {
    for (int e = blockIdx.x * blockDim.x + threadIdx.x; e < E;
         e += gridDim.x * blockDim.x) {
        int tg = etgt[e];
        int p = atomicAdd(&g_pos[tg], 1);
        g_sortpos[e] = p;
        g_stgt[p] = tg;
    }
}

// K1: P = h @ W1 + b ; zero pooled ; (optionally) zero ctx
__global__ __launch_bounds__(128) void k_initP(
    const float* __restrict__ hext, int use_gh,
    const float* __restrict__ W1, const float* __restrict__ b,
    int N, int zero_ctx)
{
    __shared__ float sA[HD * APAD];
    __shared__ float sW[HD * HD];
    const float* hsrc = use_gh ? g_h : hext;
    int t = threadIdx.x;
    int nb = blockIdx.x * TILE;
    stage_xT(hsrc + (size_t)nb * HD, sA, min(TILE, N - nb));
    stage_w(W1, sW);
    __syncthreads();
    int e0 = (t >> 4) * 4, f0 = (t & 15) * 4;
    u64 acc[2][4] = {};
    gemm_tile(sA, sW, e0, f0, acc);
    float v[4][4]; acc_to_rows(acc, v);
    float4 bv = *(const float4*)(b + f0);
#pragma unroll
    for (int i = 0; i < 4; i++) {
        int n = nb + e0 + i;
        if (n < N)
            *(float4*)(g_P + (size_t)n * HD + f0) =
                make_float4(v[i][0] + bv.x, v[i][1] + bv.y, v[i][2] + bv.z, v[i][3] + bv.w);
    }
#pragma unroll
    for (int i = 0; i < 4; i++) {
        int flat = 4 * (t + 128 * i);
        int r = flat >> 6;
        if (nb + r < N)
            *(float4*)(g_pool + (size_t)nb * HD + flat) = make_float4(0.f, 0.f, 0.f, 0.f);
    }
    if (zero_ctx && blockIdx.x == 0)
        for (int i = t; i < NG * HD; i += 128) g_ctx[i] = 0.f;
}

// K2: persistent double-buffered cp.async edge kernel (streaming emb order).
// msg = relu(P[src] + emb @ W2) ; STG.64 into g_msg at sorted slot (NO atomics).
__global__ __launch_bounds__(128) void k_edge_stg(
    const float* __restrict__ emb, const int* __restrict__ esrc,
    const float* __restrict__ W2, long long E)
{
    extern __shared__ uint dsm[];
    uint* sW  = dsm;                          // [HD * SST] tf32 W2^T [n][k]
    uint* sA  = dsm + HD * SST;               // [2][ETILE * SST] raw fp32 bits
    int*  sid = (int*)(dsm + HD * SST + 2 * ETILE * SST);  // [2][2*ETILE]: src, pos

    int t = threadIdx.x;
    uint sA_base = (uint)__cvta_generic_to_shared(sA);

#pragma unroll
    for (int i = 0; i < 8; i++) {
        int flat = 4 * t + 512 * i;
        int k = flat >> 6, n = flat & 63;
        float4 v = *(const float4*)(W2 + flat);
        sW[(n + 0) * SST + k] = to_tf32(v.x);
        sW[(n + 1) * SST + k] = to_tf32(v.y);
        sW[(n + 2) * SST + k] = to_tf32(v.z);
        sW[(n + 3) * SST + k] = to_tf32(v.w);
    }

    int lane = t & 31;
    int gid4 = lane >> 2;
    int tig  = lane & 3;
    int r0   = (t >> 5) * 16;

    long long nt_total = (E + ETILE - 1) / ETILE;
    long long tile = blockIdx.x;
    int buf = 0;

    if (tile < nt_total) {
        long long eb = tile * ETILE;
#pragma unroll
        for (int i = 0; i < 8; i++) {
            int chunk = t + 128 * i;
            int r = chunk >> 4, c = chunk & 15;
            long long row = eb + r; if (row >= E) row = E - 1;
            cpa16(sA_base + (uint)((r * SST + 4 * c) * 4), emb + row * HD + 4 * c);
        }
        if (t < ETILE) {
            long long e = eb + t;
            sid[t]         = (e < E) ? esrc[e] : 0;
            sid[ETILE + t] = (e < E) ? g_sortpos[e] : 0;
        }
    }
    CP_COMMIT();

    while (tile < nt_total) {
        long long nxt = tile + gridDim.x;
        if (nxt < nt_total) {
            long long eb = nxt * ETILE;
            uint dbase = sA_base + (uint)((buf ^ 1) * ETILE * SST * 4);
#pragma unroll
            for (int i = 0; i < 8; i++) {
                int chunk = t + 128 * i;
                int r = chunk >> 4, c = chunk & 15;
                long long row = eb + r; if (row >= E) row = E - 1;
                cpa16(dbase + (uint)((r * SST + 4 * c) * 4), emb + row * HD + 4 * c);
            }
            if (t < ETILE) {
                long long e = eb + t;
                sid[(buf ^ 1) * 2 * ETILE + t]         = (e < E) ? esrc[e] : 0;
                sid[(buf ^ 1) * 2 * ETILE + ETILE + t] = (e < E) ? g_sortpos[e] : 0;
            }
        }
        CP_COMMIT();
        asm volatile("cp.async.wait_group 1;" ::: "memory");
        __syncthreads();

        long long eb = tile * ETILE;
        const uint* A = sA + buf * ETILE * SST;
        const int* id = sid + buf * 2 * ETILE;

        float acc[8][4] = {};
        const uint* aR0 = A + (r0 + gid4) * SST;
        const uint* aR1 = aR0 + 8 * SST;
#pragma unroll
        for (int kk = 0; kk < 8; kk++) {
            int ca = kk * 8 + tig;
            uint a0 = aR0[ca], a1 = aR1[ca], a2 = aR0[ca + 4], a3 = aR1[ca + 4];
#pragma unroll
            for (int nt = 0; nt < 8; nt++) {
                const uint* bp = sW + (nt * 8 + gid4) * SST + ca;
                mma_tf32(acc[nt], a0, a1, a2, a3, bp[0], bp[4]);
            }
        }

        // epilogue: relu(P[src] + acc) -> plain STG.64 into sorted slot
#pragma unroll
        for (int p = 0; p < 2; p++) {
            int row = r0 + gid4 + 8 * p;
            if (eb + row < E) {
                int s = id[row];
                int pos = id[ETILE + row];
                const float* Ps = g_P + (size_t)s * HD;
                float* Mg = g_msg + (size_t)pos * HD;
#pragma unroll
                for (int nt = 0; nt < 8; nt++) {
                    int col = nt * 8 + 2 * tig;
                    float2 pv = *(const float2*)(Ps + col);
                    float2 m = make_float2(fmaxf(acc[nt][2 * p + 0] + pv.x, 0.f),
                                           fmaxf(acc[nt][2 * p + 1] + pv.y, 0.f));
                    *(float2*)(Mg + col) = m;
                }
            }
        }
        __syncthreads();
        buf ^= 1;
        tile = nxt;
    }
}

// K2b: streaming segmented sum over sorted messages -> pooled.
// 256 threads = 4 groups of 64; each group walks CHUNK sorted rows.
__global__ __launch_bounds__(256) void k_segsum(int E) {
    int grp = blockIdx.x * 4 + (threadIdx.x >> 6);
    int f = threadIdx.x & 63;
    int r0 = grp * CHUNK;
    if (r0 >= E) return;
    int r1 = min(r0 + CHUNK, E);
    int cur = g_stgt[r0];
    int first = 1;
    float carry = 0.f;
    int r = r0;
    while (r < r1) {
        int m = min(r1 - r, 4);
        float v[4]; int tg[4];
#pragma unroll
        for (int i = 0; i < 4; i++)
            if (i < m) { v[i] = g_msg[(size_t)(r + i) * HD + f]; tg[i] = g_stgt[r + i]; }
#pragma unroll
        for (int i = 0; i < 4; i++) {
            if (i < m) {
                if (tg[i] != cur) {
                    if (first) { atomicAdd(&g_pool[(size_t)cur * HD + f], carry); first = 0; }
                    else g_pool[(size_t)cur * HD + f] = carry;
                    carry = 0.f; cur = tg[i];
                }
                carry += v[i];
            }
        }
        r += m;
    }
    atomicAdd(&g_pool[(size_t)cur * HD + f], carry);  // last segment may span chunks
}

// K3: h = LayerNorm(relu(h + h@Wres[0:64] + pooled@Wres[64:128] + b))
__global__ __launch_bounds__(128) void k_node(
    const float* __restrict__ hext, int use_gh,
    const float* __restrict__ Wres, const float* __restrict__ bres,
    const float* __restrict__ gam, const float* __restrict__ bet, int N)
{
    __shared__ float sA[HD * APAD];
    __shared__ float sW[HD * HD];
    const float* hin = use_gh ? g_h : hext;
    int t = threadIdx.x;
    int nb = blockIdx.x * TILE;
    int valid = min(TILE, N - nb);
    int e0 = (t >> 4) * 4, f0 = (t & 15) * 4;
    u64 acc[2][4] = {};

    stage_xT(hin + (size_t)nb * HD, sA, valid);
    stage_w(Wres, sW);
    __syncthreads();
    gemm_tile(sA, sW, e0, f0, acc);
    __syncthreads();
    stage_xT(g_pool + (size_t)nb * HD, sA, valid);
    stage_w(Wres + 4096, sW);
    __syncthreads();
    gemm_tile(sA, sW, e0, f0, acc);

    float v[4][4]; acc_to_rows(acc, v);
    float4 bv = *(const float4*)(bres + f0);
    float4 gv = *(const float4*)(gam + f0);
    float4 btv = *(const float4*)(bet + f0);
#pragma unroll
    for (int i = 0; i < 4; i++) {
        int n = nb + e0 + i;
        float4 hv = make_float4(0.f, 0.f, 0.f, 0.f);
        if (n < N) hv = *(const float4*)(hin + (size_t)n * HD + f0);
        float x0 = fmaxf(v[i][0] + hv.x + bv.x, 0.f);
        float x1 = fmaxf(v[i][1] + hv.y + bv.y, 0.f);
        float x2 = fmaxf(v[i][2] + hv.z + bv.z, 0.f);
        float x3 = fmaxf(v[i][3] + hv.w + bv.w, 0.f);
        float s = x0 + x1 + x2 + x3;
        float s2 = x0 * x0 + x1 * x1 + x2 * x2 + x3 * x3;
#pragma unroll
        for (int o = 8; o; o >>= 1) {
            s  += __shfl_xor_sync(0xffffffffu, s, o);
            s2 += __shfl_xor_sync(0xffffffffu, s2, o);
        }
        float mean = s * 0.015625f;
        float var = fmaf(-mean, mean, s2 * 0.015625f);
        float rs = rsqrtf(var + LN_EPS);
        if (n < N) {
            float4 o4 = make_float4((x0 - mean) * rs * gv.x + btv.x,
                                    (x1 - mean) * rs * gv.y + btv.y,
                                    (x2 - mean) * rs * gv.z + btv.z,
                                    (x3 - mean) * rs * gv.w + btv.w);
            *(float4*)(g_h + (size_t)n * HD + f0) = o4;
        }
    }
}

// K4: per-graph sums
__global__ __launch_bounds__(512) void k_pool(const int* __restrict__ gid, int N) {
    int t = threadIdx.x;
    int f = t & 63;
    int sub = t >> 6;
    int base = blockIdx.x * 1024 + sub * 128;
    if (base >= N) return;
    int end = min(base + 128, N);
    int cur = gid[base];
    float sum = 0.f;
    for (int n = base; n < end; n++) {
        int g = gid[n];
        if (g != cur) { atomicAdd(&g_ctx[cur * HD + f], sum); sum = 0.f; cur = g; }
        sum += g_h[(size_t)n * HD + f];
    }
    atomicAdd(&g_ctx[cur * HD + f], sum);
}

// K5: divide by counts
__global__ void k_final(const int* __restrict__ gid, float* __restrict__ out, int N) {
    int t = threadIdx.x;
    int g = t >> 6;
    int lo = 0, hi = N;
    while (lo < hi) { int m = (lo + hi) >> 1; if (gid[m] < g) lo = m + 1; else hi = m; }
    int lo2 = lo, hi2 = N;
    while (lo2 < hi2) { int m = (lo2 + hi2) >> 1; if (gid[m] < g + 1) lo2 = m + 1; else hi2 = m; }
    float c = (float)(hi2 - lo);
    out[t] = g_ctx[t] / fmaxf(c, 1.f);
}

extern "C" void kernel_launch(void* const* d_in, const int* in_sizes, int n_in,
                              void* d_out, int out_size) {
    const float* h0    = (const float*)d_in[0];
    const float* emb   = (const float*)d_in[1];
    const int*   esrc  = (const int*)d_in[2];
    const int*   etgt  = (const int*)d_in[3];
    const int*   gid   = (const int*)d_in[4];
    const float* Wmsg  = (const float*)d_in[5];
    const float* bmsg  = (const float*)d_in[6];
    const float* Wres  = (const float*)d_in[7];
    const float* bres  = (const float*)d_in[8];
    const float* gamma = (const float*)d_in[9];
    const float* beta  = (const float*)d_in[10];
    float* out = (float*)d_out;

    int N = in_sizes[0] / HD;
    long long E = (long long)in_sizes[1] / HD;
    int nbN = (N + TILE - 1) / TILE;
    int segGrid = (int)(((E + CHUNK - 1) / CHUNK + 3) / 4);
    const int EDGE_SMEM = (HD * SST + 2 * ETILE * SST + 2 * 2 * ETILE) * 4;

    cudaFuncSetAttribute(k_edge_stg, cudaFuncAttributeMaxDynamicSharedMemorySize,
                         EDGE_SMEM);

    // slim sort-by-target (once; reused by both hops)
    k_zero_deg<<<(N + 1023) / 1024, 1024>>>(N);
    k_hist<<<1024, 256>>>(etgt, (int)E);
    k_scan<<<1, 1024>>>(N);
    k_scatter<<<1024, 256>>>(etgt, (int)E);

    // hop 0
    k_initP<<<nbN, 128>>>(h0, 0, Wmsg, bmsg, N, 1);
    k_edge_stg<<<EDGE_GRID, 128, EDGE_SMEM>>>(emb, esrc, Wmsg + 4096, E);
    k_segsum<<<segGrid, 256>>>((int)E);
    k_node<<<nbN, 128>>>(h0, 0, Wres, bres, gamma, beta, N);
    // hop 1
    k_initP<<<nbN, 128>>>(nullptr, 1, Wmsg + 8192, bmsg + 64, N, 0);
    k_edge_stg<<<EDGE_GRID, 128, EDGE_SMEM>>>(emb, esrc, Wmsg + 8192 + 4096, E);
    k_segsum<<<segGrid, 256>>>((int)E);
    k_node<<<nbN, 128>>>(nullptr, 1, Wres + 8192, bres + 64, gamma, beta, N);
    // pooling
    k_pool<<<(N + 1023) / 1024, 512>>>(gid, N);
    k_final<<<1, 1024>>>(gid, out, N);
}

// round 8
// speedup vs baseline: 2.0604x; 2.0604x over previous
#include <cuda_runtime.h>

#define HD 64
#define NG 16
#define TILE 32
#define ETILE 64
#define APAD 34
#define SST 68
#define EW (ETILE * SST)     // 4352 words per 64x68 tile
#define LN_EPS 1e-3f
#define NMAX 100000
#define EDGE_GRID 296        // 148 SMs x 2 CTAs

typedef unsigned long long u64;
typedef unsigned int uint;

// persistent scratch (device globals; allocation is forbidden)
__device__ float g_h[NMAX * HD];
__device__ float g_P[NMAX * HD];
__device__ float g_pool[NMAX * HD];
__device__ float g_ctx[NG * HD];

// ---------------- helpers ----------------
__device__ __forceinline__ u64 dup2(float x) {
    u64 r; unsigned xi = __float_as_uint(x);
    asm("mov.b64 %0, {%1, %1};" : "=l"(r) : "r"(xi));
    return r;
}
__device__ __forceinline__ float2 unpack2(u64 v) {
    unsigned lo, hi;
    asm("mov.b64 {%0, %1}, %2;" : "=r"(lo), "=r"(hi) : "l"(v));
    return make_float2(__uint_as_float(lo), __uint_as_float(hi));
}
__device__ __forceinline__ void ffma2(u64& d, u64 a, u64 b) {
    asm("fma.rn.f32x2 %0, %1, %2, %0;" : "+l"(d) : "l"(a), "l"(b));
}
__device__ __forceinline__ void redv2(float* p, float x, float y) {
    asm volatile("red.global.add.v2.f32 [%0], {%1,%2};"
                 :: "l"(p), "f"(x), "f"(y) : "memory");
}
__device__ __forceinline__ uint to_tf32(float f) {
    uint r; asm("cvt.rna.tf32.f32 %0, %1;" : "=r"(r) : "f"(f));
    return r;
}
__device__ __forceinline__ void mma_tf32(float c[4], uint a0, uint a1, uint a2, uint a3,
                                         uint b0, uint b1) {
    asm("mma.sync.aligned.m16n8k8.row.col.f32.tf32.tf32.f32 "
        "{%0,%1,%2,%3}, {%4,%5,%6,%7}, {%8,%9}, {%0,%1,%2,%3};"
        : "+f"(c[0]), "+f"(c[1]), "+f"(c[2]), "+f"(c[3])
        : "r"(a0), "r"(a1), "r"(a2), "r"(a3), "r"(b0), "r"(b1));
}
__device__ __forceinline__ void cpa16(uint dst, const void* src) {
    asm volatile("cp.async.ca.shared.global [%0], [%1], 16;" :: "r"(dst), "l"(src));
}
#define CP_COMMIT() asm volatile("cp.async.commit_group;" ::: "memory")
#define CP_WAIT0()  asm volatile("cp.async.wait_group 0;" ::: "memory")

// ---------------- fp32 SIMT GEMM pieces (node-side kernels) ----------------
__device__ __forceinline__ void stage_w(const float* __restrict__ W, float* sW) {
    int t = threadIdx.x;
    float4* d4 = (float4*)sW;
    const float4* s4 = (const float4*)W;
#pragma unroll
    for (int i = 0; i < 8; i++) d4[t + i * 128] = s4[t + i * 128];
}
__device__ __forceinline__ void stage_xT(const float* __restrict__ X, float* sA, int valid) {
    int t = threadIdx.x;
#pragma unroll
    for (int i = 0; i < 4; i++) {
        int flat = 4 * t + 512 * i;
        int r = flat >> 6, k = flat & 63;
        float4 v = make_float4(0.f, 0.f, 0.f, 0.f);
        if (r < valid) v = *(const float4*)(X + flat);
        sA[(k + 0) * APAD + r] = v.x;
        sA[(k + 1) * APAD + r] = v.y;
        sA[(k + 2) * APAD + r] = v.z;
        sA[(k + 3) * APAD + r] = v.w;
    }
}
__device__ __forceinline__ void gemm_tile(const float* sA, const float* sW,
                                          int e0, int f0, u64 acc[2][4]) {
    const float* pA = sA + e0;
    const float* pW = sW + f0;
#pragma unroll 8
    for (int k = 0; k < 64; k++) {
        u64 a01 = *(const u64*)(pA);
        u64 a23 = *(const u64*)(pA + 2);
        float4 w = *(const float4*)(pW);
        u64 w0 = dup2(w.x), w1 = dup2(w.y), w2 = dup2(w.z), w3 = dup2(w.w);
        ffma2(acc[0][0], a01, w0); ffma2(acc[1][0], a23, w0);
        ffma2(acc[0][1], a01, w1); ffma2(acc[1][1], a23, w1);
        ffma2(acc[0][2], a01, w2); ffma2(acc[1][2], a23, w2);
        ffma2(acc[0][3], a01, w3); ffma2(acc[1][3], a23, w3);
        pA += APAD; pW += 64;
    }
}
__device__ __forceinline__ void acc_to_rows(u64 acc[2][4], float v[4][4]) {
#pragma unroll
    for (int p = 0; p < 2; p++)
#pragma unroll
        for (int j = 0; j < 4; j++) {
            float2 u = unpack2(acc[p][j]);
            v[2 * p][j] = u.x;
            v[2 * p + 1][j] = u.y;
        }
}

// K1: P = h @ W1 + b ; zero pooled ; (optionally) zero ctx
__global__ __launch_bounds__(128) void k_initP(
    const float* __restrict__ hext, int use_gh,
    const float* __restrict__ W1, const float* __restrict__ b,
    int N, int zero_ctx)
{
    __shared__ float sA[HD * APAD];
    __shared__ float sW[HD * HD];
    const float* hsrc = use_gh ? g_h : hext;
    int t = threadIdx.x;
    int nb = blockIdx.x * TILE;
    stage_xT(hsrc + (size_t)nb * HD, sA, min(TILE, N - nb));
    stage_w(W1, sW);
    __syncthreads();
    int e0 = (t >> 4) * 4, f0 = (t & 15) * 4;
    u64 acc[2][4] = {};
    gemm_tile(sA, sW, e0, f0, acc);
    float v[4][4]; acc_to_rows(acc, v);
    float4 bv = *(const float4*)(b + f0);
#pragma unroll
    for (int i = 0; i < 4; i++) {
        int n = nb + e0 + i;
        if (n < N)
            *(float4*)(g_P + (size_t)n * HD + f0) =
                make_float4(v[i][0] + bv.x, v[i][1] + bv.y, v[i][2] + bv.z, v[i][3] + bv.w);
    }
#pragma unroll
    for (int i = 0; i < 4; i++) {
        int flat = 4 * (t + 128 * i);
        int r = flat >> 6;
        if (nb + r < N)
            *(float4*)(g_pool + (size_t)nb * HD + flat) = make_float4(0.f, 0.f, 0.f, 0.f);
    }
    if (zero_ctx && blockIdx.x == 0)
        for (int i = t; i < NG * HD; i += 128) g_ctx[i] = 0.f;
}

// K2: persistent edge kernel, 256 threads, cp.async pipeline for emb AND P-gather.
// msg = relu(P[src] + emb @ W2) ; red.v2 into pool[tgt] (L2-resident).
__global__ __launch_bounds__(256) void k_edge(
    const float* __restrict__ emb, const int* __restrict__ esrc,
    const int* __restrict__ etgt, const float* __restrict__ W2,
    int E, int N)
{
    extern __shared__ uint dsm[];
    uint*  sWf = dsm;                    // [4096] fragment-ordered tf32 W2
    uint*  sA  = dsm + 4096;             // [2][EW] emb raw fp32 bits
    float* sP  = (float*)(dsm + 4096 + 2 * EW);  // [2][EW] gathered P rows
    int*   sid = (int*)(dsm + 4096 + 4 * EW);    // [4][128]: src(64), tgt(64)

    int t = threadIdx.x;
    uint bA = (uint)__cvta_generic_to_shared(sA);
    uint bP = (uint)__cvta_generic_to_shared(sP);
    uint bI = (uint)__cvta_generic_to_shared(sid);

    // stage W2 [k][n] 64x64 into fragment order:
    // sWf[((kk*8+nt)*8+g4)*8 + tig*2 + h] = tf32(W2[(kk*8+tig+4h)*64 + nt*8+g4])
#pragma unroll
    for (int i = 0; i < 16; i++) {
        int flat = 256 * i + t;
        int h = flat & 1, tg = (flat >> 1) & 3, g4 = (flat >> 3) & 7;
        int nt = (flat >> 6) & 7, kk = (flat >> 9) & 7;
        sWf[((kk * 8 + nt) * 8 + g4) * 8 + tg * 2 + h] =
            to_tf32(W2[(kk * 8 + tg + 4 * h) * 64 + nt * 8 + g4]);
    }

    int ntiles = (E + ETILE - 1) / ETILE;
    int bid = blockIdx.x, grid = gridDim.x;

    auto stage_ids = [&](int jj) {
        int tile = bid + jj * grid;
        if (tile >= ntiles) return;
        int eb = tile * ETILE;
        int slot = jj & 3;
        if (eb + ETILE <= E) {
            if (t < 16)       cpa16(bI + (uint)((slot * 128 + 4 * t) * 4), esrc + eb + 4 * t);
            else if (t < 32)  cpa16(bI + (uint)((slot * 128 + 64 + 4 * (t - 16)) * 4),
                                    etgt + eb + 4 * (t - 16));
        } else if (t < 64) {  // rare partial tile: synchronous fill
            int e = eb + t;
            sid[slot * 128 + t]      = (e < E) ? esrc[e] : 0;
            sid[slot * 128 + 64 + t] = (e < E) ? etgt[e] : 0;
        }
    };
    auto stage_data = [&](int jj) {
        int tile = bid + jj * grid;
        if (tile >= ntiles) return;
        int eb = tile * ETILE;
        int buf = jj & 1, slot = jj & 3;
#pragma unroll
        for (int i = 0; i < 4; i++) {
            int chunk = t + 256 * i;            // 0..1023
            int r = chunk >> 4, c4 = (chunk & 15) * 4;
            int row = eb + r; if (row >= E) row = E - 1;
            cpa16(bA + (uint)((buf * EW + r * SST + c4) * 4),
                  emb + (size_t)row * HD + c4);
            int s = sid[slot * 128 + r];
            if ((uint)s >= (uint)N) s = 0;
            cpa16(bP + (uint)((buf * EW + r * SST + c4) * 4),
                  g_P + (size_t)s * HD + c4);
        }
    };

    // prologue
    stage_ids(0); stage_ids(1); CP_COMMIT();
    CP_WAIT0(); __syncthreads();
    stage_data(0); stage_ids(2); CP_COMMIT();

    int lane = t & 31;
    int gid4 = lane >> 2;
    int tig  = lane & 3;
    int w    = t >> 5;
    int r0   = (w & 3) * 16;      // warp's edge-row base
    int nb4  = (w >> 2) * 4;      // warp's nt base (0 or 4)

    for (int j = 0; ; j++) {
        int tile = bid + j * grid;
        if (tile >= ntiles) break;
        CP_WAIT0(); __syncthreads();
        stage_data(j + 1); stage_ids(j + 3); CP_COMMIT();

        int eb = tile * ETILE;
        const uint*  A = sA + (j & 1) * EW;
        const float* P = sP + (j & 1) * EW;
        const int*   id = sid + (j & 3) * 128;

        float acc[4][4] = {};
        const uint* aR0 = A + (r0 + gid4) * SST;
        const uint* aR1 = aR0 + 8 * SST;
#pragma unroll
        for (int kk = 0; kk < 8; kk++) {
            int ca = kk * 8 + tig;
            uint a0 = aR0[ca], a1 = aR1[ca], a2 = aR0[ca + 4], a3 = aR1[ca + 4];
#pragma unroll
            for (int nt = 0; nt < 4; nt++) {
                uint2 b = *(const uint2*)(sWf + ((kk * 8 + nb4 + nt) * 8 + gid4) * 8 + tig * 2);
                mma_tf32(acc[nt], a0, a1, a2, a3, b.x, b.y);
            }
        }

        // epilogue: relu(P + acc) -> red.v2 to pool[tgt]; P from smem
#pragma unroll
        for (int p = 0; p < 2; p++) {
            int row = r0 + gid4 + 8 * p;
            if (eb + row < E) {
                int g = id[64 + row];
                float* Pg = g_pool + (size_t)g * HD;
                const float* Ps = P + row * SST;
#pragma unroll
                for (int nt = 0; nt < 4; nt++) {
                    int col = (nb4 + nt) * 8 + 2 * tig;
                    float2 pv = *(const float2*)(Ps + col);
                    float m0 = fmaxf(acc[nt][2 * p + 0] + pv.x, 0.f);
                    float m1 = fmaxf(acc[nt][2 * p + 1] + pv.y, 0.f);
                    redv2(Pg + col, m0, m1);
                }
            }
        }
        // buffer reuse protection happens at next iteration's wait+sync
    }
}

// K3: h = LayerNorm(relu(h + h@Wres[0:64] + pooled@Wres[64:128] + b))
__global__ __launch_bounds__(128) void k_node(
    const float* __restrict__ hext, int use_gh,
    const float* __restrict__ Wres, const float* __restrict__ bres,
    const float* __restrict__ gam, const float* __restrict__ bet, int N)
{
    __shared__ float sA[HD * APAD];
    __shared__ float sW[HD * HD];
    const float* hin = use_gh ? g_h : hext;
    int t = threadIdx.x;
    int nb = blockIdx.x * TILE;
    int valid = min(TILE, N - nb);
    int e0 = (t >> 4) * 4, f0 = (t & 15) * 4;
    u64 acc[2][4] = {};

    stage_xT(hin + (size_t)nb * HD, sA, valid);
    stage_w(Wres, sW);
    __syncthreads();
    gemm_tile(sA, sW, e0, f0, acc);
    __syncthreads();
    stage_xT(g_pool + (size_t)nb * HD, sA, valid);
    stage_w(Wres + 4096, sW);
    __syncthreads();
    gemm_tile(sA, sW, e0, f0, acc);

    float v[4][4]; acc_to_rows(acc, v);
    float4 bv = *(const float4*)(bres + f0);
    float4 gv = *(const float4*)(gam + f0);
    float4 btv = *(const float4*)(bet + f0);
#pragma unroll
    for (int i = 0; i < 4; i++) {
        int n = nb + e0 + i;
        float4 hv = make_float4(0.f, 0.f, 0.f, 0.f);
        if (n < N) hv = *(const float4*)(hin + (size_t)n * HD + f0);
        float x0 = fmaxf(v[i][0] + hv.x + bv.x, 0.f);
        float x1 = fmaxf(v[i][1] + hv.y + bv.y, 0.f);
        float x2 = fmaxf(v[i][2] + hv.z + bv.z, 0.f);
        float x3 = fmaxf(v[i][3] + hv.w + bv.w, 0.f);
        float s = x0 + x1 + x2 + x3;
        float s2 = x0 * x0 + x1 * x1 + x2 * x2 + x3 * x3;
#pragma unroll
        for (int o = 8; o; o >>= 1) {
            s  += __shfl_xor_sync(0xffffffffu, s, o);
            s2 += __shfl_xor_sync(0xffffffffu, s2, o);
        }
        float mean = s * 0.015625f;
        float var = fmaf(-mean, mean, s2 * 0.015625f);
        float rs = rsqrtf(var + LN_EPS);
        if (n < N) {
            float4 o4 = make_float4((x0 - mean) * rs * gv.x + btv.x,
                                    (x1 - mean) * rs * gv.y + btv.y,
                                    (x2 - mean) * rs * gv.z + btv.z,
                                    (x3 - mean) * rs * gv.w + btv.w);
            *(float4*)(g_h + (size_t)n * HD + f0) = o4;
        }
    }
}

// K4: per-graph sums
__global__ __launch_bounds__(512) void k_pool(const int* __restrict__ gid, int N) {
    int t = threadIdx.x;
    int f = t & 63;
    int sub = t >> 6;
    int base = blockIdx.x * 1024 + sub * 128;
    if (base >= N) return;
    int end = min(base + 128, N);
    int cur = gid[base];
    float sum = 0.f;
    for (int n = base; n < end; n++) {
        int g = gid[n];
        if (g != cur) { atomicAdd(&g_ctx[cur * HD + f], sum); sum = 0.f; cur = g; }
        sum += g_h[(size_t)n * HD + f];
    }
    atomicAdd(&g_ctx[cur * HD + f], sum);
}

// K5: divide by counts
__global__ void k_final(const int* __restrict__ gid, float* __restrict__ out, int N) {
    int t = threadIdx.x;
    int g = t >> 6;
    int lo = 0, hi = N;
    while (lo < hi) { int m = (lo + hi) >> 1; if (gid[m] < g) lo = m + 1; else hi = m; }
    int lo2 = lo, hi2 = N;
    while (lo2 < hi2) { int m = (lo2 + hi2) >> 1; if (gid[m] < g + 1) lo2 = m + 1; else hi2 = m; }
    float c = (float)(hi2 - lo);
    out[t] = g_ctx[t] / fmaxf(c, 1.f);
}

extern "C" void kernel_launch(void* const* d_in, const int* in_sizes, int n_in,
                              void* d_out, int out_size) {
    const float* h0    = (const float*)d_in[0];
    const float* emb   = (const float*)d_in[1];
    const int*   esrc  = (const int*)d_in[2];
    const int*   etgt  = (const int*)d_in[3];
    const int*   gid   = (const int*)d_in[4];
    const float* Wmsg  = (const float*)d_in[5];
    const float* bmsg  = (const float*)d_in[6];
    const float* Wres  = (const float*)d_in[7];
    const float* bres  = (const float*)d_in[8];
    const float* gamma = (const float*)d_in[9];
    const float* beta  = (const float*)d_in[10];
    float* out = (float*)d_out;

    int N = in_sizes[0] / HD;
    int E = in_sizes[1] / HD;
    int nbN = (N + TILE - 1) / TILE;
    const int EDGE_SMEM = (4096 + 4 * EW) * 4 + 4 * 128 * 4;  // 88064 B

    cudaFuncSetAttribute(k_edge, cudaFuncAttributeMaxDynamicSharedMemorySize, EDGE_SMEM);

    // hop 0
    k_initP<<<nbN, 128>>>(h0, 0, Wmsg, bmsg, N, 1);
    k_edge<<<EDGE_GRID, 256, EDGE_SMEM>>>(emb, esrc, etgt, Wmsg + 4096, E, N);
    k_node<<<nbN, 128>>>(h0, 0, Wres, bres, gamma, beta, N);
    // hop 1
    k_initP<<<nbN, 128>>>(nullptr, 1, Wmsg + 8192, bmsg + 64, N, 0);
    k_edge<<<EDGE_GRID, 256, EDGE_SMEM>>>(emb, esrc, etgt, Wmsg + 8192 + 4096, E, N);
    k_node<<<nbN, 128>>>(nullptr, 1, Wres + 8192, bres + 64, gamma, beta, N);
    // pooling
    k_pool<<<(N + 1023) / 1024, 512>>>(gid, N);
    k_final<<<1, 1024>>>(gid, out, N);
}

// round 9
// speedup vs baseline: 2.3710x; 1.1507x over previous
#include <cuda_runtime.h>

#define HD 64
#define NG 16
#define TILE 32
#define ETILE 64
#define APAD 34
#define SST 68
#define EW (ETILE * SST)
#define LN_EPS 1e-3f
#define NMAX 100000
#define EDGE_GRID 296

typedef unsigned long long u64;
typedef unsigned int uint;

__device__ float g_h[NMAX * HD];
__device__ float g_P[NMAX * HD];
__device__ float g_pool[NMAX * HD];
__device__ float g_ctx[NG * HD];

// ---------------- helpers ----------------
__device__ __forceinline__ u64 dup2(float x) {
    u64 r; unsigned xi = __float_as_uint(x);
    asm("mov.b64 %0, {%1, %1};" : "=l"(r) : "r"(xi));
    return r;
}
__device__ __forceinline__ float2 unpack2(u64 v) {
    unsigned lo, hi;
    asm("mov.b64 {%0, %1}, %2;" : "=r"(lo), "=r"(hi) : "l"(v));
    return make_float2(__uint_as_float(lo), __uint_as_float(hi));
}
__device__ __forceinline__ void ffma2(u64& d, u64 a, u64 b) {
    asm("fma.rn.f32x2 %0, %1, %2, %0;" : "+l"(d) : "l"(a), "l"(b));
}
__device__ __forceinline__ void redv2(float* p, float x, float y) {
    asm volatile("red.global.add.v2.f32 [%0], {%1,%2};"
                 :: "l"(p), "f"(x), "f"(y) : "memory");
}
__device__ __forceinline__ uint to_tf32(float f) {
    uint r; asm("cvt.rna.tf32.f32 %0, %1;" : "=r"(r) : "f"(f));
    return r;
}
__device__ __forceinline__ void mma_tf32(float c[4], uint a0, uint a1, uint a2, uint a3,
                                         uint b0, uint b1) {
    asm("mma.sync.aligned.m16n8k8.row.col.f32.tf32.tf32.f32 "
        "{%0,%1,%2,%3}, {%4,%5,%6,%7}, {%8,%9}, {%0,%1,%2,%3};"
        : "+f"(c[0]), "+f"(c[1]), "+f"(c[2]), "+f"(c[3])
        : "r"(a0), "r"(a1), "r"(a2), "r"(a3), "r"(b0), "r"(b1));
}
__device__ __forceinline__ void cpa16(uint dst, const void* src) {
    asm volatile("cp.async.ca.shared.global [%0], [%1], 16;" :: "r"(dst), "l"(src));
}
#define CP_COMMIT() asm volatile("cp.async.commit_group;" ::: "memory")
#define CP_WAIT0()  asm volatile("cp.async.wait_group 0;" ::: "memory")

// ---------------- fp32 SIMT GEMM pieces (node-side kernels) ----------------
__device__ __forceinline__ void stage_w(const float* __restrict__ W, float* sW) {
    int t = threadIdx.x;
    float4* d4 = (float4*)sW;
    const float4* s4 = (const float4*)W;
#pragma unroll
    for (int i = 0; i < 8; i++) d4[t + i * 128] = s4[t + i * 128];
}
__device__ __forceinline__ void stage_xT(const float* __restrict__ X, float* sA, int valid) {
    int t = threadIdx.x;
#pragma unroll
    for (int i = 0; i < 4; i++) {
        int flat = 4 * t + 512 * i;
        int r = flat >> 6, k = flat & 63;
        float4 v = make_float4(0.f, 0.f, 0.f, 0.f);
        if (r < valid) v = *(const float4*)(X + flat);
        sA[(k + 0) * APAD + r] = v.x;
        sA[(k + 1) * APAD + r] = v.y;
        sA[(k + 2) * APAD + r] = v.z;
        sA[(k + 3) * APAD + r] = v.w;
    }
}
__device__ __forceinline__ void gemm_tile(const float* sA, const float* sW,
                                          int e0, int f0, u64 acc[2][4]) {
    const float* pA = sA + e0;
    const float* pW = sW + f0;
#pragma unroll 8
    for (int k = 0; k < 64; k++) {
        u64 a01 = *(const u64*)(pA);
        u64 a23 = *(const u64*)(pA + 2);
        float4 w = *(const float4*)(pW);
        u64 w0 = dup2(w.x), w1 = dup2(w.y), w2 = dup2(w.z), w3 = dup2(w.w);
        ffma2(acc[0][0], a01, w0); ffma2(acc[1][0], a23, w0);
        ffma2(acc[0][1], a01, w1); ffma2(acc[1][1], a23, w1);
        ffma2(acc[0][2], a01, w2); ffma2(acc[1][2], a23, w2);
        ffma2(acc[0][3], a01, w3); ffma2(acc[1][3], a23, w3);
        pA += APAD; pW += 64;
    }
}
__device__ __forceinline__ void acc_to_rows(u64 acc[2][4], float v[4][4]) {
#pragma unroll
    for (int p = 0; p < 2; p++)
#pragma unroll
        for (int j = 0; j < 4; j++) {
            float2 u = unpack2(acc[p][j]);
            v[2 * p][j] = u.x;
            v[2 * p + 1][j] = u.y;
        }
}

// K1: P = h0 @ W1 + b ; zero pooled ; zero ctx (hop 0 only)
__global__ __launch_bounds__(128) void k_initP(
    const float* __restrict__ hext,
    const float* __restrict__ W1, const float* __restrict__ b, int N)
{
    __shared__ float sA[HD * APAD];
    __shared__ float sW[HD * HD];
    int t = threadIdx.x;
    int nb = blockIdx.x * TILE;
    stage_xT(hext + (size_t)nb * HD, sA, min(TILE, N - nb));
    stage_w(W1, sW);
    __syncthreads();
    int e0 = (t >> 4) * 4, f0 = (t & 15) * 4;
    u64 acc[2][4] = {};
    gemm_tile(sA, sW, e0, f0, acc);
    float v[4][4]; acc_to_rows(acc, v);
    float4 bv = *(const float4*)(b + f0);
#pragma unroll
    for (int i = 0; i < 4; i++) {
        int n = nb + e0 + i;
        if (n < N)
            *(float4*)(g_P + (size_t)n * HD + f0) =
                make_float4(v[i][0] + bv.x, v[i][1] + bv.y, v[i][2] + bv.z, v[i][3] + bv.w);
    }
#pragma unroll
    for (int i = 0; i < 4; i++) {
        int flat = 4 * (t + 128 * i);
        int r = flat >> 6;
        if (nb + r < N)
            *(float4*)(g_pool + (size_t)nb * HD + flat) = make_float4(0.f, 0.f, 0.f, 0.f);
    }
    if (blockIdx.x == 0)
        for (int i = t; i < NG * HD; i += 128) g_ctx[i] = 0.f;
}

// K2: persistent edge kernel; W2 fragments in registers; cp.async pipeline emb+P.
__global__ __launch_bounds__(256, 2) void k_edge(
    const float* __restrict__ emb, const int* __restrict__ esrc,
    const int* __restrict__ etgt, const float* __restrict__ W2,
    int E, int N)
{
    extern __shared__ uint dsm[];
    uint*  sA  = dsm;                         // [2][EW] emb raw fp32 bits
    float* sP  = (float*)(dsm + 2 * EW);      // [2][EW] gathered P rows
    int*   sid = (int*)(dsm + 4 * EW);        // [4][128]: src(64), tgt(64)

    int t = threadIdx.x;
    uint bA = (uint)__cvta_generic_to_shared(sA);
    uint bP = (uint)__cvta_generic_to_shared(sP);
    uint bI = (uint)__cvta_generic_to_shared(sid);

    int lane = t & 31;
    int gid4 = lane >> 2;
    int tig  = lane & 3;
    int w    = t >> 5;
    int r0   = (w & 3) * 16;
    int nb4  = (w >> 2) * 4;

    // stage W2 (coalesced) into sA scratch, then pull fragments to registers
    {
        uint* scratch = dsm;  // 4096 uints
#pragma unroll
        for (int i = 0; i < 16; i++) scratch[t + 256 * i] = __float_as_uint(W2[t + 256 * i]);
        __syncthreads();
    }
    uint2 wB[8][4];
#pragma unroll
    for (int kk = 0; kk < 8; kk++)
#pragma unroll
        for (int nt = 0; nt < 4; nt++) {
            int n = (nb4 + nt) * 8 + gid4;
            wB[kk][nt].x = to_tf32(__uint_as_float(dsm[(kk * 8 + tig) * 64 + n]));
            wB[kk][nt].y = to_tf32(__uint_as_float(dsm[(kk * 8 + tig + 4) * 64 + n]));
        }
    __syncthreads();

    int ntiles = (E + ETILE - 1) / ETILE;
    int bid = blockIdx.x, grid = gridDim.x;

    auto stage_ids = [&](int jj) {
        int tile = bid + jj * grid;
        if (tile >= ntiles) return;
        int eb = tile * ETILE;
        int slot = jj & 3;
        if (eb + ETILE <= E) {
            if (t < 16)       cpa16(bI + (uint)((slot * 128 + 4 * t) * 4), esrc + eb + 4 * t);
            else if (t < 32)  cpa16(bI + (uint)((slot * 128 + 64 + 4 * (t - 16)) * 4),
                                    etgt + eb + 4 * (t - 16));
        } else if (t < 64) {
            int e = eb + t;
            sid[slot * 128 + t]      = (e < E) ? esrc[e] : 0;
            sid[slot * 128 + 64 + t] = (e < E) ? etgt[e] : 0;
        }
    };
    auto stage_data = [&](int jj) {
        int tile = bid + jj * grid;
        if (tile >= ntiles) return;
        int eb = tile * ETILE;
        int buf = jj & 1, slot = jj & 3;
#pragma unroll
        for (int i = 0; i < 4; i++) {
            int chunk = t + 256 * i;
            int r = chunk >> 4, c4 = (chunk & 15) * 4;
            int row = eb + r; if (row >= E) row = E - 1;
            cpa16(bA + (uint)((buf * EW + r * SST + c4) * 4),
                  emb + (size_t)row * HD + c4);
            int s = sid[slot * 128 + r];
            if ((uint)s >= (uint)N) s = 0;
            cpa16(bP + (uint)((buf * EW + r * SST + c4) * 4),
                  g_P + (size_t)s * HD + c4);
        }
    };

    stage_ids(0); stage_ids(1); CP_COMMIT();
    CP_WAIT0(); __syncthreads();
    stage_data(0); stage_ids(2); CP_COMMIT();

    for (int j = 0; ; j++) {
        int tile = bid + j * grid;
        if (tile >= ntiles) break;
        CP_WAIT0(); __syncthreads();
        stage_data(j + 1); stage_ids(j + 3); CP_COMMIT();

        int eb = tile * ETILE;
        const uint*  A = sA + (j & 1) * EW;
        const float* P = sP + (j & 1) * EW;
        const int*   id = sid + (j & 3) * 128;

        float acc[4][4] = {};
        const uint* aR0 = A + (r0 + gid4) * SST;
        const uint* aR1 = aR0 + 8 * SST;
#pragma unroll
        for (int kk = 0; kk < 8; kk++) {
            int ca = kk * 8 + tig;
            uint a0 = aR0[ca], a1 = aR1[ca], a2 = aR0[ca + 4], a3 = aR1[ca + 4];
#pragma unroll
            for (int nt = 0; nt < 4; nt++)
                mma_tf32(acc[nt], a0, a1, a2, a3, wB[kk][nt].x, wB[kk][nt].y);
        }

#pragma unroll
        for (int p = 0; p < 2; p++) {
            int row = r0 + gid4 + 8 * p;
            if (eb + row < E) {
                int g = id[64 + row];
                float* Pg = g_pool + (size_t)g * HD;
                const float* Ps = P + row * SST;
#pragma unroll
                for (int nt = 0; nt < 4; nt++) {
                    int col = (nb4 + nt) * 8 + 2 * tig;
                    float2 pv = *(const float2*)(Ps + col);
                    float m0 = fmaxf(acc[nt][2 * p + 0] + pv.x, 0.f);
                    float m1 = fmaxf(acc[nt][2 * p + 1] + pv.y, 0.f);
                    redv2(Pg + col, m0, m1);
                }
            }
        }
    }
}

// K3: h = LN(relu(h + h@Wres[0:64] + pooled@Wres[64:128] + b));
// optionally fused: P_next = h_new @ W1n + bn, zero pool.
__global__ __launch_bounds__(128) void k_node(
    const float* __restrict__ hext, int use_gh,
    const float* __restrict__ Wres, const float* __restrict__ bres,
    const float* __restrict__ gam, const float* __restrict__ bet,
    const float* __restrict__ W1n, const float* __restrict__ bn,
    int do_next, int N)
{
    __shared__ float sA[HD * APAD];
    __shared__ float sW[HD * HD];
    const float* hin = use_gh ? g_h : hext;
    int t = threadIdx.x;
    int nb = blockIdx.x * TILE;
    int valid = min(TILE, N - nb);
    int e0 = (t >> 4) * 4, f0 = (t & 15) * 4;
    u64 acc[2][4] = {};

    stage_xT(hin + (size_t)nb * HD, sA, valid);
    stage_w(Wres, sW);
    __syncthreads();
    gemm_tile(sA, sW, e0, f0, acc);
    __syncthreads();
    stage_xT(g_pool + (size_t)nb * HD, sA, valid);
    stage_w(Wres + 4096, sW);
    __syncthreads();
    gemm_tile(sA, sW, e0, f0, acc);

    float v[4][4]; acc_to_rows(acc, v);
    float4 bv = *(const float4*)(bres + f0);
    float4 gv = *(const float4*)(gam + f0);
    float4 btv = *(const float4*)(bet + f0);
    float o[4][4];
#pragma unroll
    for (int i = 0; i < 4; i++) {
        int n = nb + e0 + i;
        float4 hv = make_float4(0.f, 0.f, 0.f, 0.f);
        if (n < N) hv = *(const float4*)(hin + (size_t)n * HD + f0);
        float x0 = fmaxf(v[i][0] + hv.x + bv.x, 0.f);
        float x1 = fmaxf(v[i][1] + hv.y + bv.y, 0.f);
        float x2 = fmaxf(v[i][2] + hv.z + bv.z, 0.f);
        float x3 = fmaxf(v[i][3] + hv.w + bv.w, 0.f);
        float s = x0 + x1 + x2 + x3;
        float s2 = x0 * x0 + x1 * x1 + x2 * x2 + x3 * x3;
#pragma unroll
        for (int os = 8; os; os >>= 1) {
            s  += __shfl_xor_sync(0xffffffffu, s, os);
            s2 += __shfl_xor_sync(0xffffffffu, s2, os);
        }
        float mean = s * 0.015625f;
        float var = fmaf(-mean, mean, s2 * 0.015625f);
        float rs = rsqrtf(var + LN_EPS);
        o[i][0] = (x0 - mean) * rs * gv.x + btv.x;
        o[i][1] = (x1 - mean) * rs * gv.y + btv.y;
        o[i][2] = (x2 - mean) * rs * gv.z + btv.z;
        o[i][3] = (x3 - mean) * rs * gv.w + btv.w;
        if (n < N)
            *(float4*)(g_h + (size_t)n * HD + f0) =
                make_float4(o[i][0], o[i][1], o[i][2], o[i][3]);
        else { o[i][0] = o[i][1] = o[i][2] = o[i][3] = 0.f; }
    }

    if (!do_next) return;

    // fused: P_next = h_new @ W1n + bn ; zero pool rows
    __syncthreads();   // all gemm reads of sA/sW complete
#pragma unroll
    for (int i = 0; i < 4; i++)
#pragma unroll
        for (int jj = 0; jj < 4; jj++)
            sA[(f0 + jj) * APAD + (e0 + i)] = o[i][jj];
    stage_w(W1n, sW);
    __syncthreads();
    u64 acc2[2][4] = {};
    gemm_tile(sA, sW, e0, f0, acc2);
    float v2[4][4]; acc_to_rows(acc2, v2);
    float4 bnv = *(const float4*)(bn + f0);
#pragma unroll
    for (int i = 0; i < 4; i++) {
        int n = nb + e0 + i;
        if (n < N)
            *(float4*)(g_P + (size_t)n * HD + f0) =
                make_float4(v2[i][0] + bnv.x, v2[i][1] + bnv.y,
                            v2[i][2] + bnv.z, v2[i][3] + bnv.w);
    }
#pragma unroll
    for (int i = 0; i < 4; i++) {
        int flat = 4 * (t + 128 * i);
        int r = flat >> 6;
        if (nb + r < N)
            *(float4*)(g_pool + (size_t)nb * HD + flat) = make_float4(0.f, 0.f, 0.f, 0.f);
    }
}

// K4: per-graph sums
__global__ __launch_bounds__(512) void k_pool(const int* __restrict__ gid, int N) {
    int t = threadIdx.x;
    int f = t & 63;
    int sub = t >> 6;
    int base = blockIdx.x * 1024 + sub * 128;
    if (base >= N) return;
    int end = min(base + 128, N);
    int cur = gid[base];
    float sum = 0.f;
    for (int n = base; n < end; n++) {
        int g = gid[n];
        if (g != cur) { atomicAdd(&g_ctx[cur * HD + f], sum); sum = 0.f; cur = g; }
        sum += g_h[(size_t)n * HD + f];
    }
    atomicAdd(&g_ctx[cur * HD + f], sum);
}

// K5: divide by counts
__global__ void k_final(const int* __restrict__ gid, float* __restrict__ out, int N) {
    int t = threadIdx.x;
    int g = t >> 6;
    int lo = 0, hi = N;
    while (lo < hi) { int m = (lo + hi) >> 1; if (gid[m] < g) lo = m + 1; else hi = m; }
    int lo2 = lo, hi2 = N;
    while (lo2 < hi2) { int m = (lo2 + hi2) >> 1; if (gid[m] < g + 1) lo2 = m + 1; else hi2 = m; }
    float c = (float)(hi2 - lo);
    out[t] = g_ctx[t] / fmaxf(c, 1.f);
}

extern "C" void kernel_launch(void* const* d_in, const int* in_sizes, int n_in,
                              void* d_out, int out_size) {
    const float* h0    = (const float*)d_in[0];
    const float* emb   = (const float*)d_in[1];
    const int*   esrc  = (const int*)d_in[2];
    const int*   etgt  = (const int*)d_in[3];
    const int*   gid   = (const int*)d_in[4];
    const float* Wmsg  = (const float*)d_in[5];
    const float* bmsg  = (const float*)d_in[6];
    const float* Wres  = (const float*)d_in[7];
    const float* bres  = (const float*)d_in[8];
    const float* gamma = (const float*)d_in[9];
    const float* beta  = (const float*)d_in[10];
    float* out = (float*)d_out;

    int N = in_sizes[0] / HD;
    int E = in_sizes[1] / HD;
    int nbN = (N + TILE - 1) / TILE;
    const int EDGE_SMEM = 4 * EW * 4 + 4 * 128 * 4;  // 71680 B

    cudaFuncSetAttribute(k_edge, cudaFuncAttributeMaxDynamicSharedMemorySize, EDGE_SMEM);

    // hop 0
    k_initP<<<nbN, 128>>>(h0, Wmsg, bmsg, N);
    k_edge<<<EDGE_GRID, 256, EDGE_SMEM>>>(emb, esrc, etgt, Wmsg + 4096, E, N);
    // node hop0 + fused P for hop1 + zero pool
    k_node<<<nbN, 128>>>(h0, 0, Wres, bres, gamma, beta,
                         Wmsg + 8192, bmsg + 64, 1, N);
    // hop 1
    k_edge<<<EDGE_GRID, 256, EDGE_SMEM>>>(emb, esrc, etgt, Wmsg + 8192 + 4096, E, N);
    k_node<<<nbN, 128>>>(nullptr, 1, Wres + 8192, bres + 64, gamma, beta,
                         nullptr, nullptr, 0, N);
    // pooling
    k_pool<<<(N + 1023) / 1024, 512>>>(gid, N);
    k_final<<<1, 1024>>>(gid, out, N);
}

// round 10
// speedup vs baseline: 2.7195x; 1.1470x over previous
#include <cuda_runtime.h>

#define HD 64
#define NG 16
#define ETILE 64
#define SST 68
#define EW (ETILE * SST)
#define LN_EPS 1e-3f
#define NMAX 100000
#define EDGE_GRID 296
#define NODE_GRID 296

typedef unsigned long long u64;
typedef unsigned int uint;

__device__ float g_h[NMAX * HD];
__device__ float g_P[NMAX * HD];
__device__ float g_pool[NMAX * HD];
__device__ float g_ctx[NG * HD];

// ---------------- helpers ----------------
__device__ __forceinline__ void redv2(float* p, float x, float y) {
    asm volatile("red.global.add.v2.f32 [%0], {%1,%2};"
                 :: "l"(p), "f"(x), "f"(y) : "memory");
}
__device__ __forceinline__ uint to_tf32(float f) {
    uint r; asm("cvt.rna.tf32.f32 %0, %1;" : "=r"(r) : "f"(f));
    return r;
}
__device__ __forceinline__ void mma_tf32(float c[4], uint a0, uint a1, uint a2, uint a3,
                                         uint b0, uint b1) {
    asm("mma.sync.aligned.m16n8k8.row.col.f32.tf32.tf32.f32 "
        "{%0,%1,%2,%3}, {%4,%5,%6,%7}, {%8,%9}, {%0,%1,%2,%3};"
        : "+f"(c[0]), "+f"(c[1]), "+f"(c[2]), "+f"(c[3])
        : "r"(a0), "r"(a1), "r"(a2), "r"(a3), "r"(b0), "r"(b1));
}
__device__ __forceinline__ void cpa16(uint dst, const void* src) {
    asm volatile("cp.async.ca.shared.global [%0], [%1], 16;" :: "r"(dst), "l"(src));
}
#define CP_COMMIT() asm volatile("cp.async.commit_group;" ::: "memory")
#define CP_WAIT0()  asm volatile("cp.async.wait_group 0;" ::: "memory")

// stage 64x64 W into fragment-ordered tf32 smem (dst[flat] pattern; coalesced STS)
__device__ __forceinline__ void stage_wfrag(const float* __restrict__ W, uint* dst, int t) {
#pragma unroll
    for (int i = 0; i < 16; i++) {
        int flat = t + 256 * i;
        int h = flat & 1, tg = (flat >> 1) & 3, g4 = (flat >> 3) & 7;
        int nt = (flat >> 6) & 7, kk = (flat >> 9) & 7;
        dst[flat] = to_tf32(W[(kk * 8 + tg + 4 * h) * 64 + nt * 8 + g4]);
    }
}

// 64x64x64 tf32 mma mainloop: A raw-fp32 in smem (stride SST), W frags in smem
__device__ __forceinline__ void mma_loop(const uint* __restrict__ X,
                                         const uint* __restrict__ Wf,
                                         int r0, int gid4, int tig, int nb4,
                                         float acc[4][4]) {
    const uint* aR0 = X + (r0 + gid4) * SST;
    const uint* aR1 = aR0 + 8 * SST;
#pragma unroll
    for (int kk = 0; kk < 8; kk++) {
        int ca = kk * 8 + tig;
        uint a0 = aR0[ca], a1 = aR1[ca], a2 = aR0[ca + 4], a3 = aR1[ca + 4];
#pragma unroll
        for (int nt = 0; nt < 4; nt++) {
            uint2 b = *(const uint2*)(Wf + ((kk * 8 + nb4 + nt) * 8 + gid4) * 8 + tig * 2);
            mma_tf32(acc[nt], a0, a1, a2, a3, b.x, b.y);
        }
    }
}

// ---------------- fused node kernel (tf32 mma) ----------------
// mode 0: P = h0 @ Wn + bn ; zero pool ; zero ctx
// mode 1: h=LN(relu(h+[h,pool]@Wres+bres)) ; P = h_new @ Wn + bn ; zero pool
// mode 2: h=LN(relu(h+[h,pool]@Wres+bres)) only
__global__ __launch_bounds__(256, 2) void k_node_mma(
    const float* __restrict__ hext, int use_gh, int mode,
    const float* __restrict__ Wres, const float* __restrict__ bres,
    const float* __restrict__ gam, const float* __restrict__ bet,
    const float* __restrict__ Wn, const float* __restrict__ bn, int N)
{
    extern __shared__ uint sm[];
    uint* sWh = sm;                 // [4096] Wres rows 0..63 frags
    uint* sWp = sm + 4096;          // [4096] Wres rows 64..127 frags
    uint* sWn = sm + 8192;          // [4096] Wn frags
    uint* sH  = sm + 12288;         // [4352] h tile raw fp32
    uint* sPo = sm + 16640;         // [4352] pool tile raw fp32
    float2* sRed = (float2*)(sm + 20992);  // [128] LN partials

    int t = threadIdx.x;
    const float* hin = use_gh ? g_h : hext;

    if (mode != 0) { stage_wfrag(Wres, sWh, t); stage_wfrag(Wres + 4096, sWp, t); }
    if (mode != 2) stage_wfrag(Wn, sWn, t);
    if (mode == 0 && blockIdx.x == 0)
        for (int i = t; i < NG * HD; i += 256) g_ctx[i] = 0.f;

    int lane = t & 31, gid4 = lane >> 2, tig = lane & 3;
    int w = t >> 5, rw = w & 3, nh = w >> 2;
    int r0 = rw * 16, nb4 = nh * 4;

    float2 vb[4], vg[4], vbt[4], vbn[4];
#pragma unroll
    for (int nt = 0; nt < 4; nt++) {
        int c = (nb4 + nt) * 8 + 2 * tig;
        vb[nt]  = *(const float2*)(bres + c);
        vg[nt]  = *(const float2*)(gam + c);
        vbt[nt] = *(const float2*)(bet + c);
        vbn[nt] = *(const float2*)(bn + c);
    }
    __syncthreads();

    uint bH = (uint)__cvta_generic_to_shared(sH);
    uint bP = (uint)__cvta_generic_to_shared(sPo);
    int ntiles = (N + 63) >> 6;

    for (int tile = blockIdx.x; tile < ntiles; tile += gridDim.x) {
        int nb = tile << 6;
        __syncthreads();  // previous tile's smem readers done
        // stage h tile (+pool tile): contiguous streams
#pragma unroll
        for (int i = 0; i < 4; i++) {
            int chunk = t + 256 * i;
            int r = chunk >> 4, c4 = (chunk & 15) * 4;
            int row = nb + r; if (row >= N) row = N - 1;
            cpa16(bH + (uint)((r * SST + c4) * 4), hin + (size_t)row * HD + c4);
            if (mode) cpa16(bP + (uint)((r * SST + c4) * 4), g_pool + (size_t)row * HD + c4);
        }
        CP_COMMIT(); CP_WAIT0(); __syncthreads();

        if (mode != 0) {
            float acc[4][4] = {};
            mma_loop(sH, sWh, r0, gid4, tig, nb4, acc);
            mma_loop(sPo, sWp, r0, gid4, tig, nb4, acc);

            // x = relu(h + acc + bres); per-row partial sums
            float x[4][4];
            float s[2] = {0.f, 0.f}, s2[2] = {0.f, 0.f};
#pragma unroll
            for (int p = 0; p < 2; p++) {
                int row = r0 + gid4 + 8 * p;
#pragma unroll
                for (int nt = 0; nt < 4; nt++) {
                    int c = (nb4 + nt) * 8 + 2 * tig;
                    float2 hv = *(const float2*)((const float*)sH + row * SST + c);
                    float x0 = fmaxf(acc[nt][2 * p + 0] + hv.x + vb[nt].x, 0.f);
                    float x1 = fmaxf(acc[nt][2 * p + 1] + hv.y + vb[nt].y, 0.f);
                    x[nt][2 * p] = x0; x[nt][2 * p + 1] = x1;
                    s[p] += x0 + x1;
                    s2[p] += x0 * x0 + x1 * x1;
                }
            }
            // reduce over tig (lane bits 0..1)
#pragma unroll
            for (int o = 1; o <= 2; o <<= 1) {
#pragma unroll
                for (int p = 0; p < 2; p++) {
                    s[p]  += __shfl_xor_sync(0xffffffffu, s[p], o);
                    s2[p] += __shfl_xor_sync(0xffffffffu, s2[p], o);
                }
            }
            if (tig == 0) {
                sRed[nh * 64 + r0 + gid4]     = make_float2(s[0], s2[0]);
                sRed[nh * 64 + r0 + gid4 + 8] = make_float2(s[1], s2[1]);
            }
            __syncthreads();
#pragma unroll
            for (int p = 0; p < 2; p++) {
                int row = r0 + gid4 + 8 * p;
                float2 ra = sRed[row], rb = sRed[64 + row];
                float fs = ra.x + rb.x, fs2 = ra.y + rb.y;
                float mean = fs * 0.015625f;
                float var = fmaf(-mean, mean, fs2 * 0.015625f);
                float rsd = rsqrtf(var + LN_EPS);
                int n = nb + row;
#pragma unroll
                for (int nt = 0; nt < 4; nt++) {
                    int c = (nb4 + nt) * 8 + 2 * tig;
                    float xn0 = (x[nt][2 * p] - mean) * rsd * vg[nt].x + vbt[nt].x;
                    float xn1 = (x[nt][2 * p + 1] - mean) * rsd * vg[nt].y + vbt[nt].y;
                    if (n < N)
                        *(float2*)(g_h + (size_t)n * HD + c) = make_float2(xn0, xn1);
                    if (mode == 1)
                        *(float2*)((float*)sH + row * SST + c) = make_float2(xn0, xn1);
                }
            }
            if (mode == 1) __syncthreads();  // xn tile visible for next gemm
        }

        if (mode != 2) {
            float acc2[4][4] = {};
            mma_loop(sH, sWn, r0, gid4, tig, nb4, acc2);
#pragma unroll
            for (int p = 0; p < 2; p++) {
                int row = r0 + gid4 + 8 * p;
                int n = nb + row;
                if (n < N) {
#pragma unroll
                    for (int nt = 0; nt < 4; nt++) {
                        int c = (nb4 + nt) * 8 + 2 * tig;
                        *(float2*)(g_P + (size_t)n * HD + c) =
                            make_float2(acc2[nt][2 * p] + vbn[nt].x,
                                        acc2[nt][2 * p + 1] + vbn[nt].y);
                    }
                }
            }
            // zero pool rows of this tile
#pragma unroll
            for (int i = 0; i < 4; i++) {
                int id = t + 256 * i;
                int r = id >> 4, c4 = (id & 15) * 4;
                int n = nb + r;
                if (n < N)
                    *(float4*)(g_pool + (size_t)n * HD + c4) = make_float4(0.f, 0.f, 0.f, 0.f);
            }
        }
    }
}

// ---------------- edge kernel (unchanged from R9 winner) ----------------
__global__ __launch_bounds__(256, 2) void k_edge(
    const float* __restrict__ emb, const int* __restrict__ esrc,
    const int* __restrict__ etgt, const float* __restrict__ W2,
    int E, int N)
{
    extern __shared__ uint dsm[];
    uint*  sA  = dsm;
    float* sP  = (float*)(dsm + 2 * EW);
    int*   sid = (int*)(dsm + 4 * EW);

    int t = threadIdx.x;
    uint bA = (uint)__cvta_generic_to_shared(sA);
    uint bP = (uint)__cvta_generic_to_shared(sP);
    uint bI = (uint)__cvta_generic_to_shared(sid);

    int lane = t & 31;
    int gid4 = lane >> 2;
    int tig  = lane & 3;
    int w    = t >> 5;
    int r0   = (w & 3) * 16;
    int nb4  = (w >> 2) * 4;

    {
        uint* scratch = dsm;
#pragma unroll
        for (int i = 0; i < 16; i++) scratch[t + 256 * i] = __float_as_uint(W2[t + 256 * i]);
        __syncthreads();
    }
    uint2 wB[8][4];
#pragma unroll
    for (int kk = 0; kk < 8; kk++)
#pragma unroll
        for (int nt = 0; nt < 4; nt++) {
            int n = (nb4 + nt) * 8 + gid4;
            wB[kk][nt].x = to_tf32(__uint_as_float(dsm[(kk * 8 + tig) * 64 + n]));
            wB[kk][nt].y = to_tf32(__uint_as_float(dsm[(kk * 8 + tig + 4) * 64 + n]));
        }
    __syncthreads();

    int ntiles = (E + ETILE - 1) / ETILE;
    int bid = blockIdx.x, grid = gridDim.x;

    auto stage_ids = [&](int jj) {
        int tile = bid + jj * grid;
        if (tile >= ntiles) return;
        int eb = tile * ETILE;
        int slot = jj & 3;
        if (eb + ETILE <= E) {
            if (t < 16)       cpa16(bI + (uint)((slot * 128 + 4 * t) * 4), esrc + eb + 4 * t);
            else if (t < 32)  cpa16(bI + (uint)((slot * 128 + 64 + 4 * (t - 16)) * 4),
                                    etgt + eb + 4 * (t - 16));
        } else if (t < 64) {
            int e = eb + t;
            sid[slot * 128 + t]      = (e < E) ? esrc[e] : 0;
            sid[slot * 128 + 64 + t] = (e < E) ? etgt[e] : 0;
        }
    };
    auto stage_data = [&](int jj) {
        int tile = bid + jj * grid;
        if (tile >= ntiles) return;
        int eb = tile * ETILE;
        int buf = jj & 1, slot = jj & 3;
#pragma unroll
        for (int i = 0; i < 4; i++) {
            int chunk = t + 256 * i;
            int r = chunk >> 4, c4 = (chunk & 15) * 4;
            int row = eb + r; if (row >= E) row = E - 1;
            cpa16(bA + (uint)((buf * EW + r * SST + c4) * 4),
                  emb + (size_t)row * HD + c4);
            int s = sid[slot * 128 + r];
            if ((uint)s >= (uint)N) s = 0;
            cpa16(bP + (uint)((buf * EW + r * SST + c4) * 4),
                  g_P + (size_t)s * HD + c4);
        }
    };

    stage_ids(0); stage_ids(1); CP_COMMIT();
    CP_WAIT0(); __syncthreads();
    stage_data(0); stage_ids(2); CP_COMMIT();

    for (int j = 0; ; j++) {
        int tile = bid + j * grid;
        if (tile >= ntiles) break;
        CP_WAIT0(); __syncthreads();
        stage_data(j + 1); stage_ids(j + 3); CP_COMMIT();

        int eb = tile * ETILE;
        const uint*  A = sA + (j & 1) * EW;
        const float* P = sP + (j & 1) * EW;
        const int*   id = sid + (j & 3) * 128;

        float acc[4][4] = {};
        const uint* aR0 = A + (r0 + gid4) * SST;
        const uint* aR1 = aR0 + 8 * SST;
#pragma unroll
        for (int kk = 0; kk < 8; kk++) {
            int ca = kk * 8 + tig;
            uint a0 = aR0[ca], a1 = aR1[ca], a2 = aR0[ca + 4], a3 = aR1[ca + 4];
#pragma unroll
            for (int nt = 0; nt < 4; nt++)
                mma_tf32(acc[nt], a0, a1, a2, a3, wB[kk][nt].x, wB[kk][nt].y);
        }

#pragma unroll
        for (int p = 0; p < 2; p++) {
            int row = r0 + gid4 + 8 * p;
            if (eb + row < E) {
                int g = id[64 + row];
                float* Pg = g_pool + (size_t)g * HD;
                const float* Ps = P + row * SST;
#pragma unroll
                for (int nt = 0; nt < 4; nt++) {
                    int col = (nb4 + nt) * 8 + 2 * tig;
                    float2 pv = *(const float2*)(Ps + col);
                    float m0 = fmaxf(acc[nt][2 * p + 0] + pv.x, 0.f);
                    float m1 = fmaxf(acc[nt][2 * p + 1] + pv.y, 0.f);
                    redv2(Pg + col, m0, m1);
                }
            }
        }
    }
}

// K4: per-graph sums
__global__ __launch_bounds__(512) void k_pool(const int* __restrict__ gid, int N) {
    int t = threadIdx.x;
    int f = t & 63;
    int sub = t >> 6;
    int base = blockIdx.x * 1024 + sub * 128;
    if (base >= N) return;
    int end = min(base + 128, N);
    int cur = gid[base];
    float sum = 0.f;
    for (int n = base; n < end; n++) {
        int g = gid[n];
        if (g != cur) { atomicAdd(&g_ctx[cur * HD + f], sum); sum = 0.f; cur = g; }
        sum += g_h[(size_t)n * HD + f];
    }
    atomicAdd(&g_ctx[cur * HD + f], sum);
}

// K5: divide by counts
__global__ void k_final(const int* __restrict__ gid, float* __restrict__ out, int N) {
    int t = threadIdx.x;
    int g = t >> 6;
    int lo = 0, hi = N;
    while (lo < hi) { int m = (lo + hi) >> 1; if (gid[m] < g) lo = m + 1; else hi = m; }
    int lo2 = lo, hi2 = N;
    while (lo2 < hi2) { int m = (lo2 + hi2) >> 1; if (gid[m] < g + 1) lo2 = m + 1; else hi2 = m; }
    float c = (float)(hi2 - lo);
    out[t] = g_ctx[t] / fmaxf(c, 1.f);
}

extern "C" void kernel_launch(void* const* d_in, const int* in_sizes, int n_in,
                              void* d_out, int out_size) {
    const float* h0    = (const float*)d_in[0];
    const float* emb   = (const float*)d_in[1];
    const int*   esrc  = (const int*)d_in[2];
    const int*   etgt  = (const int*)d_in[3];
    const int*   gid   = (const int*)d_in[4];
    const float* Wmsg  = (const float*)d_in[5];
    const float* bmsg  = (const float*)d_in[6];
    const float* Wres  = (const float*)d_in[7];
    const float* bres  = (const float*)d_in[8];
    const float* gamma = (const float*)d_in[9];
    const float* beta  = (const float*)d_in[10];
    float* out = (float*)d_out;

    int N = in_sizes[0] / HD;
    int E = in_sizes[1] / HD;
    const int EDGE_SMEM = 4 * EW * 4 + 4 * 128 * 4;   // 71680 B
    const int NODE_SMEM = 21248 * 4;                  // 84992 B

    cudaFuncSetAttribute(k_edge, cudaFuncAttributeMaxDynamicSharedMemorySize, EDGE_SMEM);
    cudaFuncSetAttribute(k_node_mma, cudaFuncAttributeMaxDynamicSharedMemorySize, NODE_SMEM);

    // hop 0
    k_node_mma<<<NODE_GRID, 256, NODE_SMEM>>>(h0, 0, 0,
        Wres, bres, gamma, beta, Wmsg, bmsg, N);                       // P0, zero pool/ctx
    k_edge<<<EDGE_GRID, 256, EDGE_SMEM>>>(emb, esrc, etgt, Wmsg + 4096, E, N);
    k_node_mma<<<NODE_GRID, 256, NODE_SMEM>>>(h0, 0, 1,
        Wres, bres, gamma, beta, Wmsg + 8192, bmsg + 64, N);           // node0 + P1
    // hop 1
    k_edge<<<EDGE_GRID, 256, EDGE_SMEM>>>(emb, esrc, etgt, Wmsg + 8192 + 4096, E, N);
    k_node_mma<<<NODE_GRID, 256, NODE_SMEM>>>(nullptr, 1, 2,
        Wres + 8192, bres + 64, gamma, beta, Wmsg, bmsg, N);           // node1
    // pooling
    k_pool<<<(N + 1023) / 1024, 512>>>(gid, N);
    k_final<<<1, 1024>>>(gid, out, N);
}

// round 11
// speedup vs baseline: 2.9935x; 1.1007x over previous
#include <cuda_runtime.h>

#define HD 64
#define NG 16
#define ETILE 64
#define SST 68            // node-kernel smem stride
#define EST 72            // edge-kernel smem stride (conflict-free for LDS.64 pattern)
#define EW (ETILE * SST)
#define EWE (ETILE * EST) // 4608
#define LN_EPS 1e-3f
#define NMAX 100000
#define EDGE_GRID 296
#define NODE_GRID 296

typedef unsigned long long u64;
typedef unsigned int uint;

__device__ float g_h[NMAX * HD];
__device__ float g_P[NMAX * HD];
__device__ float g_pool[NMAX * HD];
__device__ float g_ctx[NG * HD];

// ---------------- helpers ----------------
__device__ __forceinline__ void redv2(float* p, float x, float y) {
    asm volatile("red.global.add.v2.f32 [%0], {%1,%2};"
                 :: "l"(p), "f"(x), "f"(y) : "memory");
}
__device__ __forceinline__ uint to_tf32(float f) {
    uint r; asm("cvt.rna.tf32.f32 %0, %1;" : "=r"(r) : "f"(f));
    return r;
}
__device__ __forceinline__ void mma_tf32(float c[4], uint a0, uint a1, uint a2, uint a3,
                                         uint b0, uint b1) {
    asm("mma.sync.aligned.m16n8k8.row.col.f32.tf32.tf32.f32 "
        "{%0,%1,%2,%3}, {%4,%5,%6,%7}, {%8,%9}, {%0,%1,%2,%3};"
        : "+f"(c[0]), "+f"(c[1]), "+f"(c[2]), "+f"(c[3])
        : "r"(a0), "r"(a1), "r"(a2), "r"(a3), "r"(b0), "r"(b1));
}
__device__ __forceinline__ void cpa16(uint dst, const void* src) {
    asm volatile("cp.async.ca.shared.global [%0], [%1], 16;" :: "r"(dst), "l"(src));
}
__device__ __forceinline__ void cpg16(uint dst, const void* src) {
    asm volatile("cp.async.cg.shared.global [%0], [%1], 16;" :: "r"(dst), "l"(src));
}
#define CP_COMMIT() asm volatile("cp.async.commit_group;" ::: "memory")
#define CP_WAIT0()  asm volatile("cp.async.wait_group 0;" ::: "memory")
#define CP_WAIT1()  asm volatile("cp.async.wait_group 1;" ::: "memory")

// stage 64x64 W into fragment-ordered tf32 smem (node kernel; natural k order)
__device__ __forceinline__ void stage_wfrag(const float* __restrict__ W, uint* dst, int t) {
#pragma unroll
    for (int i = 0; i < 16; i++) {
        int flat = t + 256 * i;
        int h = flat & 1, tg = (flat >> 1) & 3, g4 = (flat >> 3) & 7;
        int nt = (flat >> 6) & 7, kk = (flat >> 9) & 7;
        dst[flat] = to_tf32(W[(kk * 8 + tg + 4 * h) * 64 + nt * 8 + g4]);
    }
}

// node-kernel mma mainloop (A stride SST, natural k order)
__device__ __forceinline__ void mma_loop(const uint* __restrict__ X,
                                         const uint* __restrict__ Wf,
                                         int r0, int gid4, int tig, int nb4,
                                         float acc[4][4]) {
    const uint* aR0 = X + (r0 + gid4) * SST;
    const uint* aR1 = aR0 + 8 * SST;
#pragma unroll
    for (int kk = 0; kk < 8; kk++) {
        int ca = kk * 8 + tig;
        uint a0 = aR0[ca], a1 = aR1[ca], a2 = aR0[ca + 4], a3 = aR1[ca + 4];
#pragma unroll
        for (int nt = 0; nt < 4; nt++) {
            uint2 b = *(const uint2*)(Wf + ((kk * 8 + nb4 + nt) * 8 + gid4) * 8 + tig * 2);
            mma_tf32(acc[nt], a0, a1, a2, a3, b.x, b.y);
        }
    }
}

// ---------------- fused node kernel (unchanged from R10 winner) ----------------
__global__ __launch_bounds__(256, 2) void k_node_mma(
    const float* __restrict__ hext, int use_gh, int mode,
    const float* __restrict__ Wres, const float* __restrict__ bres,
    const float* __restrict__ gam, const float* __restrict__ bet,
    const float* __restrict__ Wn, const float* __restrict__ bn, int N)
{
    extern __shared__ uint sm[];
    uint* sWh = sm;
    uint* sWp = sm + 4096;
    uint* sWn = sm + 8192;
    uint* sH  = sm + 12288;
    uint* sPo = sm + 16640;
    float2* sRed = (float2*)(sm + 20992);

    int t = threadIdx.x;
    const float* hin = use_gh ? g_h : hext;

    if (mode != 0) { stage_wfrag(Wres, sWh, t); stage_wfrag(Wres + 4096, sWp, t); }
    if (mode != 2) stage_wfrag(Wn, sWn, t);
    if (mode == 0 && blockIdx.x == 0)
        for (int i = t; i < NG * HD; i += 256) g_ctx[i] = 0.f;

    int lane = t & 31, gid4 = lane >> 2, tig = lane & 3;
    int w = t >> 5, rw = w & 3, nh = w >> 2;
    int r0 = rw * 16, nb4 = nh * 4;

    float2 vb[4], vg[4], vbt[4], vbn[4];
#pragma unroll
    for (int nt = 0; nt < 4; nt++) {
        int c = (nb4 + nt) * 8 + 2 * tig;
        vb[nt]  = *(const float2*)(bres + c);
        vg[nt]  = *(const float2*)(gam + c);
        vbt[nt] = *(const float2*)(bet + c);
        vbn[nt] = *(const float2*)(bn + c);
    }
    __syncthreads();

    uint bH = (uint)__cvta_generic_to_shared(sH);
    uint bP = (uint)__cvta_generic_to_shared(sPo);
    int ntiles = (N + 63) >> 6;

    for (int tile = blockIdx.x; tile < ntiles; tile += gridDim.x) {
        int nb = tile << 6;
        __syncthreads();
#pragma unroll
        for (int i = 0; i < 4; i++) {
            int chunk = t + 256 * i;
            int r = chunk >> 4, c4 = (chunk & 15) * 4;
            int row = nb + r; if (row >= N) row = N - 1;
            cpa16(bH + (uint)((r * SST + c4) * 4), hin + (size_t)row * HD + c4);
            if (mode) cpa16(bP + (uint)((r * SST + c4) * 4), g_pool + (size_t)row * HD + c4);
        }
        CP_COMMIT(); CP_WAIT0(); __syncthreads();

        if (mode != 0) {
            float acc[4][4] = {};
            mma_loop(sH, sWh, r0, gid4, tig, nb4, acc);
            mma_loop(sPo, sWp, r0, gid4, tig, nb4, acc);

            float x[4][4];
            float s[2] = {0.f, 0.f}, s2[2] = {0.f, 0.f};
#pragma unroll
            for (int p = 0; p < 2; p++) {
                int row = r0 + gid4 + 8 * p;
#pragma unroll
                for (int nt = 0; nt < 4; nt++) {
                    int c = (nb4 + nt) * 8 + 2 * tig;
                    float2 hv = *(const float2*)((const float*)sH + row * SST + c);
                    float x0 = fmaxf(acc[nt][2 * p + 0] + hv.x + vb[nt].x, 0.f);
                    float x1 = fmaxf(acc[nt][2 * p + 1] + hv.y + vb[nt].y, 0.f);
                    x[nt][2 * p] = x0; x[nt][2 * p + 1] = x1;
                    s[p] += x0 + x1;
                    s2[p] += x0 * x0 + x1 * x1;
                }
            }
#pragma unroll
            for (int o = 1; o <= 2; o <<= 1) {
#pragma unroll
                for (int p = 0; p < 2; p++) {
                    s[p]  += __shfl_xor_sync(0xffffffffu, s[p], o);
                    s2[p] += __shfl_xor_sync(0xffffffffu, s2[p], o);
                }
            }
            if (tig == 0) {
                sRed[nh * 64 + r0 + gid4]     = make_float2(s[0], s2[0]);
                sRed[nh * 64 + r0 + gid4 + 8] = make_float2(s[1], s2[1]);
            }
            __syncthreads();
#pragma unroll
            for (int p = 0; p < 2; p++) {
                int row = r0 + gid4 + 8 * p;
                float2 ra = sRed[row], rb = sRed[64 + row];
                float fs = ra.x + rb.x, fs2 = ra.y + rb.y;
                float mean = fs * 0.015625f;
                float var = fmaf(-mean, mean, fs2 * 0.015625f);
                float rsd = rsqrtf(var + LN_EPS);
                int n = nb + row;
#pragma unroll
                for (int nt = 0; nt < 4; nt++) {
                    int c = (nb4 + nt) * 8 + 2 * tig;
                    float xn0 = (x[nt][2 * p] - mean) * rsd * vg[nt].x + vbt[nt].x;
                    float xn1 = (x[nt][2 * p + 1] - mean) * rsd * vg[nt].y + vbt[nt].y;
                    if (n < N)
                        *(float2*)(g_h + (size_t)n * HD + c) = make_float2(xn0, xn1);
                    if (mode == 1)
                        *(float2*)((float*)sH + row * SST + c) = make_float2(xn0, xn1);
                }
            }
            if (mode == 1) __syncthreads();
        }

        if (mode != 2) {
            float acc2[4][4] = {};
            mma_loop(sH, sWn, r0, gid4, tig, nb4, acc2);
#pragma unroll
            for (int p = 0; p < 2; p++) {
                int row = r0 + gid4 + 8 * p;
                int n = nb + row;
                if (n < N) {
#pragma unroll
                    for (int nt = 0; nt < 4; nt++) {
                        int c = (nb4 + nt) * 8 + 2 * tig;
                        *(float2*)(g_P + (size_t)n * HD + c) =
                            make_float2(acc2[nt][2 * p] + vbn[nt].x,
                                        acc2[nt][2 * p + 1] + vbn[nt].y);
                    }
                }
            }
#pragma unroll
            for (int i = 0; i < 4; i++) {
                int id = t + 256 * i;
                int r = id >> 4, c4 = (id & 15) * 4;
                int n = nb + r;
                if (n < N)
                    *(float4*)(g_pool + (size_t)n * HD + c4) = make_float4(0.f, 0.f, 0.f, 0.f);
            }
        }
    }
}

// ---------------- edge kernel: triple-buffered, cg-bypass, LDS.64 A-frags ----------------
__global__ __launch_bounds__(256, 2) void k_edge(
    const float* __restrict__ emb, const int* __restrict__ esrc,
    const int* __restrict__ etgt, const float* __restrict__ W2,
    int E, int N)
{
    extern __shared__ uint dsm[];
    uint*  sA  = dsm;                       // [3][EWE] emb raw fp32 bits
    float* sP  = (float*)(dsm + 3 * EWE);   // [3][EWE] gathered P rows
    int*   sid = (int*)(dsm + 6 * EWE);     // [8][128]: src(64), tgt(64)

    int t = threadIdx.x;
    uint bA = (uint)__cvta_generic_to_shared(sA);
    uint bP = (uint)__cvta_generic_to_shared(sP);
    uint bI = (uint)__cvta_generic_to_shared(sid);

    int lane = t & 31;
    int gid4 = lane >> 2;
    int tig  = lane & 3;
    int w    = t >> 5;
    int r0   = (w & 3) * 16;
    int nb4  = (w >> 2) * 4;

    // stage W2 (coalesced) into sA scratch, then pull fragments to registers.
    // k relabelled: thread tig holds k = {2tig, 2tig+1} per kk (matches LDS.64 A loads)
    {
        uint* scratch = dsm;
#pragma unroll
        for (int i = 0; i < 16; i++) scratch[t + 256 * i] = __float_as_uint(W2[t + 256 * i]);
        __syncthreads();
    }
    uint2 wB[8][4];
#pragma unroll
    for (int kk = 0; kk < 8; kk++)
#pragma unroll
        for (int nt = 0; nt < 4; nt++) {
            int n = (nb4 + nt) * 8 + gid4;
            wB[kk][nt].x = to_tf32(__uint_as_float(dsm[(kk * 8 + 2 * tig) * 64 + n]));
            wB[kk][nt].y = to_tf32(__uint_as_float(dsm[(kk * 8 + 2 * tig + 1) * 64 + n]));
        }
    __syncthreads();

    int ntiles = (E + ETILE - 1) / ETILE;
    int bid = blockIdx.x, grid = gridDim.x;

    auto stage_ids = [&](int jj) {
        int tile = bid + jj * grid;
        if (tile >= ntiles) return;
        int eb = tile * ETILE;
        int slot = jj & 7;
        if (eb + ETILE <= E) {
            if (t < 16)       cpa16(bI + (uint)((slot * 128 + 4 * t) * 4), esrc + eb + 4 * t);
            else if (t < 32)  cpa16(bI + (uint)((slot * 128 + 64 + 4 * (t - 16)) * 4),
                                    etgt + eb + 4 * (t - 16));
        } else if (t < 64) {
            int e = eb + t;
            sid[slot * 128 + t]      = (e < E) ? esrc[e] : 0;
            sid[slot * 128 + 64 + t] = (e < E) ? etgt[e] : 0;
        }
    };
    auto stage_data = [&](int jj) {
        int tile = bid + jj * grid;
        if (tile >= ntiles) return;
        int eb = tile * ETILE;
        int buf = jj % 3, slot = jj & 7;
#pragma unroll
        for (int i = 0; i < 4; i++) {
            int chunk = t + 256 * i;
            int r = chunk >> 4, c4 = (chunk & 15) * 4;
            int row = eb + r; if (row >= E) row = E - 1;
            cpg16(bA + (uint)((buf * EWE + r * EST + c4) * 4),
                  emb + (size_t)row * HD + c4);
            int s = sid[slot * 128 + r];
            if ((uint)s >= (uint)N) s = 0;
            cpg16(bP + (uint)((buf * EWE + r * EST + c4) * 4),
                  g_P + (size_t)s * HD + c4);
        }
    };

    // prologue: ids(0..1); then data(0)+ids(2); data(1)+ids(3)
    stage_ids(0); stage_ids(1); CP_COMMIT();
    CP_WAIT0(); __syncthreads();
    stage_data(0); stage_ids(2); CP_COMMIT();
    stage_data(1); stage_ids(3); CP_COMMIT();

    for (int j = 0; ; j++) {
        int tile = bid + j * grid;
        if (tile >= ntiles) break;
        CP_WAIT1();            // data(j) + ids(j+2) complete; data(j+1) may be in flight
        __syncthreads();
        stage_data(j + 2); stage_ids(j + 4); CP_COMMIT();

        int eb = tile * ETILE;
        const uint*  A = sA + (j % 3) * EWE;
        const float* P = sP + (j % 3) * EWE;
        const int*   id = sid + (j & 7) * 128;

        float acc[4][4] = {};
        const uint* aR0 = A + (r0 + gid4) * EST;
        const uint* aR1 = aR0 + 8 * EST;
#pragma unroll
        for (int kk = 0; kk < 8; kk++) {
            int ca = kk * 8 + 2 * tig;
            uint2 A0 = *(const uint2*)(aR0 + ca);   // (row,   k=2tig), (row,   k=2tig+1)
            uint2 A1 = *(const uint2*)(aR1 + ca);   // (row+8, k=2tig), (row+8, k=2tig+1)
#pragma unroll
            for (int nt = 0; nt < 4; nt++)
                mma_tf32(acc[nt], A0.x, A1.x, A0.y, A1.y, wB[kk][nt].x, wB[kk][nt].y);
        }

#pragma unroll
        for (int p = 0; p < 2; p++) {
            int row = r0 + gid4 + 8 * p;
            if (eb + row < E) {
                int g = id[64 + row];
                float* Pg = g_pool + (size_t)g * HD;
                const float* Ps = P + row * EST;
#pragma unroll
                for (int nt = 0; nt < 4; nt++) {
                    int col = (nb4 + nt) * 8 + 2 * tig;
                    float2 pv = *(const float2*)(Ps + col);
                    float m0 = fmaxf(acc[nt][2 * p + 0] + pv.x, 0.f);
                    float m1 = fmaxf(acc[nt][2 * p + 1] + pv.y, 0.f);
                    redv2(Pg + col, m0, m1);
                }
            }
        }
    }
}

// K4: per-graph sums
__global__ __launch_bounds__(512) void k_pool(const int* __restrict__ gid, int N) {
    int t = threadIdx.x;
    int f = t & 63;
    int sub = t >> 6;
    int base = blockIdx.x * 1024 + sub * 128;
    if (base >= N) return;
    int end = min(base + 128, N);
    int cur = gid[base];
    float sum = 0.f;
    for (int n = base; n < end; n++) {
        int g = gid[n];
        if (g != cur) { atomicAdd(&g_ctx[cur * HD + f], sum); sum = 0.f; cur = g; }
        sum += g_h[(size_t)n * HD + f];
    }
    atomicAdd(&g_ctx[cur * HD + f], sum);
}

// K5: divide by counts
__global__ void k_final(const int* __restrict__ gid, float* __restrict__ out, int N) {
    int t = threadIdx.x;
    int g = t >> 6;
    int lo = 0, hi = N;
    while (lo < hi) { int m = (lo + hi) >> 1; if (gid[m] < g) lo = m + 1; else hi = m; }
    int lo2 = lo, hi2 = N;
    while (lo2 < hi2) { int m = (lo2 + hi2) >> 1; if (gid[m] < g + 1) lo2 = m + 1; else hi2 = m; }
    float c = (float)(hi2 - lo);
    out[t] = g_ctx[t] / fmaxf(c, 1.f);
}

extern "C" void kernel_launch(void* const* d_in, const int* in_sizes, int n_in,
                              void* d_out, int out_size) {
    const float* h0    = (const float*)d_in[0];
    const float* emb   = (const float*)d_in[1];
    const int*   esrc  = (const int*)d_in[2];
    const int*   etgt  = (const int*)d_in[3];
    const int*   gid   = (const int*)d_in[4];
    const float* Wmsg  = (const float*)d_in[5];
    const float* bmsg  = (const float*)d_in[6];
    const float* Wres  = (const float*)d_in[7];
    const float* bres  = (const float*)d_in[8];
    const float* gamma = (const float*)d_in[9];
    const float* beta  = (const float*)d_in[10];
    float* out = (float*)d_out;

    int N = in_sizes[0] / HD;
    int E = in_sizes[1] / HD;
    const int EDGE_SMEM = 6 * EWE * 4 + 8 * 128 * 4;  // 114688 B
    const int NODE_SMEM = 21248 * 4;                  // 84992 B

    cudaFuncSetAttribute(k_edge, cudaFuncAttributeMaxDynamicSharedMemorySize, EDGE_SMEM);
    cudaFuncSetAttribute(k_node_mma, cudaFuncAttributeMaxDynamicSharedMemorySize, NODE_SMEM);

    // hop 0
    k_node_mma<<<NODE_GRID, 256, NODE_SMEM>>>(h0, 0, 0,
        Wres, bres, gamma, beta, Wmsg, bmsg, N);
    k_edge<<<EDGE_GRID, 256, EDGE_SMEM>>>(emb, esrc, etgt, Wmsg + 4096, E, N);
    k_node_mma<<<NODE_GRID, 256, NODE_SMEM>>>(h0, 0, 1,
        Wres, bres, gamma, beta, Wmsg + 8192, bmsg + 64, N);
    // hop 1
    k_edge<<<EDGE_GRID, 256, EDGE_SMEM>>>(emb, esrc, etgt, Wmsg + 8192 + 4096, E, N);
    k_node_mma<<<NODE_GRID, 256, NODE_SMEM>>>(nullptr, 1, 2,
        Wres + 8192, bres + 64, gamma, beta, Wmsg, bmsg, N);
    // pooling
    k_pool<<<(N + 1023) / 1024, 512>>>(gid, N);
    k_final<<<1, 1024>>>(gid, out, N);
}